// round 16
// baseline (speedup 1.0000x reference)
#include <cuda_runtime.h>
#include <cuda_fp16.h>
#include <cstdint>

// Problem constants
#define BN   8192      // batch
#define FK   128       // feature dim (GEMM K)
#define DD   10000     // hypervector dim
#define CC   100       // classes
#define HV_W 320       // padded u32 words per hv row

#define MT   64        // m tiles (8192/128)
#define NT   79        // n tiles (10112 padded / 128)
#define TILE_U4 2048   // uint4 per 128x128 fp16 tile (32 KB)

// prep grid partition
#define PA_BLOCKS 512                       // prep_a: 8192 rows x 16 kgroups / 256
#define PB_BLOCKS 316                       // prep_b: 8 kg x 10112 d / 256 (exact)
#define P8_BLOCKS 79                        // proto8 tile builders
#define PREP_BLOCKS (PA_BLOCKS + PB_BLOCKS + CC + P8_BLOCKS)

// ---------------- scratch (device globals; no allocation allowed) ----------------
__device__ unsigned g_hv[BN * HV_W];            // bitpacked hypervectors (~10.5 MB)
__device__ uint4    g_proto[80 * CC];           // packed prototypes [chunk][class]
__device__ int      g_protopop[CC];             // per-class popcount
__device__ uint4    g_Abf[2 * MT * TILE_U4];    // feat 2-split fp16 planes (4 MB)
__device__ uint4    g_Bbf[NT * TILE_U4];        // R fp16, tile-image layout (2.6 MB)
__device__ uint4    g_proto8[NT * 1024];        // int8 proto tiles [t][128n x 128k sw] (1.3 MB)
__device__ unsigned g_pd[4 * BN * 64];          // k-split partial dots u16x2 packed (8.4 MB)

// ============================ helpers ==============================
__device__ __forceinline__ uint32_t smem_u32(const void* p) {
    uint32_t a;
    asm("{ .reg .u64 t; cvta.to.shared.u64 t, %1; cvt.u32.u64 %0, t; }" : "=r"(a) : "l"(p));
    return a;
}

#define CP_ASYNC16(dst, src) \
    asm volatile("cp.async.cg.shared.global [%0], [%1], 16;" :: "r"(dst), "l"(src) : "memory")
#define CP_COMMIT() asm volatile("cp.async.commit_group;" ::: "memory")
template <int N>
__device__ __forceinline__ void cp_wait() {
    asm volatile("cp.async.wait_group %0;" :: "n"(N) : "memory");
}

__device__ __forceinline__ void ldsm4(uint32_t addr, uint32_t& r0, uint32_t& r1,
                                      uint32_t& r2, uint32_t& r3) {
    asm volatile("ldmatrix.sync.aligned.m8n8.x4.shared.b16 {%0,%1,%2,%3}, [%4];"
                 : "=r"(r0), "=r"(r1), "=r"(r2), "=r"(r3) : "r"(addr));
}

__device__ __forceinline__ void mma16816(float* c, uint32_t a0, uint32_t a1,
                                         uint32_t a2, uint32_t a3,
                                         uint32_t b0, uint32_t b1) {
    asm volatile(
        "mma.sync.aligned.m16n8k16.row.col.f32.f16.f16.f32 "
        "{%0,%1,%2,%3}, {%4,%5,%6,%7}, {%8,%9}, {%0,%1,%2,%3};"
        : "+f"(c[0]), "+f"(c[1]), "+f"(c[2]), "+f"(c[3])
        : "r"(a0), "r"(a1), "r"(a2), "r"(a3), "r"(b0), "r"(b1));
}

__device__ __forceinline__ void imma16832(int* c, uint32_t a0, uint32_t a1,
                                          uint32_t a2, uint32_t a3,
                                          uint32_t b0, uint32_t b1) {
    asm volatile(
        "mma.sync.aligned.m16n8k32.row.col.s32.s8.s8.s32 "
        "{%0,%1,%2,%3}, {%4,%5,%6,%7}, {%8,%9}, {%0,%1,%2,%3};"
        : "+r"(c[0]), "+r"(c[1]), "+r"(c[2]), "+r"(c[3])
        : "r"(a0), "r"(a1), "r"(a2), "r"(a3), "r"(b0), "r"(b1));
}

// blocked-atom SW128 byte offset within a 128x128 fp16 tile (atom = 8 rows x 64 halves)
__device__ __forceinline__ uint32_t tile_off(int row, int col) {
    const uint32_t b = (uint32_t)(((row >> 3) + (col >> 6) * 16) * 1024
                                  + (row & 7) * 128 + (col & 63) * 2);
    return b ^ ((b >> 3) & 0x70);
}

__device__ __forceinline__ unsigned pack_pair(float v0, float v1, float& r0, float& r1) {
    const __half h0 = __float2half(v0);
    const __half h1 = __float2half(v1);
    r0 = v0 - __half2float(h0);
    r1 = v1 - __half2float(h1);
    return ((unsigned)__half_as_ushort(h1) << 16) | __half_as_ushort(h0);
}

// =================================================================================
// Fused prep kernel: A fp16 split, B fp16 tiles, proto bit-pack, proto8 int8 tiles.
// =================================================================================
__global__ void __launch_bounds__(256) prep_fused_kernel(const float* __restrict__ feat,
                                                         const float* __restrict__ R,
                                                         const void*  __restrict__ proto_raw)
{
    const int bx = blockIdx.x;

    if (bx < PA_BLOCKS) {
        const int idx = bx * 256 + threadIdx.x;   // 8192 * 16
        const int b   = idx >> 4;
        const int kg  = idx & 15;
        const int t   = b >> 7, m = b & 127, k0 = kg * 8;

        const float4 x0 = *(const float4*)(feat + b * FK + k0);
        const float4 x1 = *(const float4*)(feat + b * FK + k0 + 4);

        float r[8];
        uint4 w0, w1;
        w0.x = pack_pair(x0.x, x0.y, r[0], r[1]);
        w0.y = pack_pair(x0.z, x0.w, r[2], r[3]);
        w0.z = pack_pair(x1.x, x1.y, r[4], r[5]);
        w0.w = pack_pair(x1.z, x1.w, r[6], r[7]);
        float d0, d1;
        w1.x = pack_pair(r[0], r[1], d0, d1);
        w1.y = pack_pair(r[2], r[3], d0, d1);
        w1.z = pack_pair(r[4], r[5], d0, d1);
        w1.w = pack_pair(r[6], r[7], d0, d1);

        const uint32_t o16 = tile_off(m, k0) >> 4;
        g_Abf[(0 * MT + t) * TILE_U4 + o16] = w0;
        g_Abf[(1 * MT + t) * TILE_U4 + o16] = w1;
        return;
    }

    if (bx < PA_BLOCKS + PB_BLOCKS) {
        // ---- prep B: thread handles one d, 16 consecutive k (MLP=16) ----
        const int idx = (bx - PA_BLOCKS) * 256 + threadIdx.x;   // 8 * 10112 exactly
        const int kg = idx / (NT * 128);
        const int d  = idx - kg * (NT * 128);
        const int t  = d >> 7, n = d & 127, k0 = kg * 16;

        float v[16];
        #pragma unroll
        for (int kk = 0; kk < 16; kk++)
            v[kk] = (d < DD) ? R[(k0 + kk) * DD + d] : 0.0f;

        uint4 wa, wb;
        {
            float s0, s1;
            wa.x = pack_pair(v[0],  v[1],  s0, s1);
            wa.y = pack_pair(v[2],  v[3],  s0, s1);
            wa.z = pack_pair(v[4],  v[5],  s0, s1);
            wa.w = pack_pair(v[6],  v[7],  s0, s1);
            wb.x = pack_pair(v[8],  v[9],  s0, s1);
            wb.y = pack_pair(v[10], v[11], s0, s1);
            wb.z = pack_pair(v[12], v[13], s0, s1);
            wb.w = pack_pair(v[14], v[15], s0, s1);
        }
        g_Bbf[t * TILE_U4 + (tile_off(n, k0) >> 4)]     = wa;
        g_Bbf[t * TILE_U4 + (tile_off(n, k0 + 8) >> 4)] = wb;
        return;
    }

    // ---- shared dtype detector for the two proto roles ----
    const int tid = threadIdx.x;
    __shared__ int s_f32bad, s_i32bad;
    if (tid == 0) { s_f32bad = 0; s_i32bad = 0; }
    __syncthreads();
    {
        const unsigned v = ((const unsigned*)proto_raw)[tid];
        if (v != 0u && v != 0x3F800000u) atomicOr(&s_f32bad, 1);
        if (v > 1u)                      atomicOr(&s_i32bad, 1);
    }
    __syncthreads();
    const int mode = (!s_f32bad) ? 2 : ((!s_i32bad) ? 1 : 0);   // 2=f32, 1=i32, 0=u8

    const unsigned char* p8  = (const unsigned char*)proto_raw;
    const int*           p32 = (const int*)proto_raw;
    const float*         pf  = (const float*)proto_raw;

    if (bx < PA_BLOCKS + PB_BLOCKS + CC) {
        // ---------------- pack prototypes (bits) + popcount ----------------
        const int c = bx - (PA_BLOCKS + PB_BLOCKS);

        int sum = 0;
        for (int w = tid; w < HV_W; w += 256) {
            unsigned word = 0;
            if (w < 313) {
                const int dbase = w * 32;
                #pragma unroll 8
                for (int j = 0; j < 32; j++) {
                    const int d = dbase + j;
                    if (d < DD) {
                        bool bit;
                        if (mode == 2)      bit = (pf[c * DD + d] != 0.0f);
                        else if (mode == 1) bit = (p32[c * DD + d] != 0);
                        else                bit = (p8[c * DD + d] != 0);
                        if (bit) word |= (1u << j);
                    }
                }
            }
            sum += __popc(word);
            ((unsigned*)g_proto)[((w >> 2) * CC + c) * 4 + (w & 3)] = word;
        }

        __shared__ int red[256];
        red[tid] = sum;
        __syncthreads();
        #pragma unroll
        for (int s = 128; s > 0; s >>= 1) {
            if (tid < s) red[tid] += red[tid + s];
            __syncthreads();
        }
        if (tid == 0) g_protopop[c] = red[0];
        return;
    }

    // ---------------- proto8 tiles: [t][128 n x 128 k] int8, swizzled 16B slots ----
    // class 100 = all-ones (rowpop); classes 101..127 = zeros.
    {
        const int t = bx - (PA_BLOCKS + PB_BLOCKS + CC);
        #pragma unroll
        for (int i = 0; i < 4; i++) {
            const int ch = tid + i * 256;     // 0..1023
            const int n  = ch >> 3;
            const int s  = ch & 7;
            uint32_t vw[4];
            #pragma unroll
            for (int wq = 0; wq < 4; wq++) {
                uint32_t b = 0;
                #pragma unroll
                for (int bj = 0; bj < 4; bj++) {
                    const int kk = s * 16 + wq * 4 + bj;
                    const int d  = t * 128 + kk;
                    unsigned bit = 0;
                    if (n == 100) bit = 1;
                    else if (n < 100 && d < DD) {
                        if (mode == 2)      bit = (pf[n * DD + d] != 0.0f) ? 1u : 0u;
                        else if (mode == 1) bit = (p32[n * DD + d] != 0) ? 1u : 0u;
                        else                bit = (p8[n * DD + d] != 0) ? 1u : 0u;
                    }
                    b |= bit << (8 * bj);
                }
                vw[wq] = b;
            }
            g_proto8[t * 1024 + n * 8 + (s ^ (n & 7))] = make_uint4(vw[0], vw[1], vw[2], vw[3]);
        }
    }
}

// =================================================================================
// GEMM kernel (R10-proven, VERBATIM): 128x128 tile per CTA, mma.sync fp16 HMMA,
// 2 fp16 split planes fully prefetched, smem 98.3 KB -> 2 CTAs/SM. Writes g_hv.
// =================================================================================
#define SMO_A0   0
#define SMO_A1   32768
#define SMO_B    65536
#define SMO_WRD  98304
#define SM_TOT   (SMO_WRD + 2048)

__global__ void __launch_bounds__(256, 2) gemm_kernel()
{
    extern __shared__ char sm[];
    const uint32_t smem_base = smem_u32(sm);
    const int tid  = threadIdx.x;
    const int lane = tid & 31, wid = tid >> 5;
    const int nt = blockIdx.x, mt = blockIdx.y;

    {
        const uint4* srcB = g_Bbf + nt * TILE_U4;
        #pragma unroll
        for (int i = 0; i < 8; i++) {
            const int j = tid + i * 256;
            CP_ASYNC16(smem_base + SMO_B + j * 16, (const void*)(srcB + j));
        }
        const uint4* srcA0 = g_Abf + (0 * MT + mt) * TILE_U4;
        #pragma unroll
        for (int i = 0; i < 8; i++) {
            const int j = tid + i * 256;
            CP_ASYNC16(smem_base + SMO_A0 + j * 16, (const void*)(srcA0 + j));
        }
        CP_COMMIT();
        const uint4* srcA1 = g_Abf + (1 * MT + mt) * TILE_U4;
        #pragma unroll
        for (int i = 0; i < 8; i++) {
            const int j = tid + i * 256;
            CP_ASYNC16(smem_base + SMO_A1 + j * 16, (const void*)(srcA1 + j));
        }
        CP_COMMIT();
    }

    const int wm = (wid & 3) * 32;
    const int wn = (wid >> 2) * 64;

    uint32_t rbA[2], sxA[2];
    #pragma unroll
    for (int mf = 0; mf < 2; mf++) {
        const int r = wm + mf * 16 + (lane & 15);
        rbA[mf] = (uint32_t)((r >> 3) * 1024 + (r & 7) * 128);
        sxA[mf] = (uint32_t)((r & 7) << 4);
    }
    const uint32_t colselA = (lane & 16) >> 1;

    uint32_t rbB[4], sxB[4];
    #pragma unroll
    for (int p = 0; p < 4; p++) {
        const int r = wn + p * 16 + (lane & 7) + ((lane & 16) >> 1);
        rbB[p] = (uint32_t)((r >> 3) * 1024 + (r & 7) * 128);
        sxB[p] = (uint32_t)((r & 7) << 4);
    }
    const uint32_t colselB = lane & 8;

    float acc[2][8][4];
    #pragma unroll
    for (int mf = 0; mf < 2; mf++)
        #pragma unroll
        for (int nf = 0; nf < 8; nf++)
            #pragma unroll
            for (int i = 0; i < 4; i++) acc[mf][nf][i] = 0.0f;

    #pragma unroll
    for (int s = 0; s < 2; s++) {
        if (s == 0) cp_wait<1>();
        else        cp_wait<0>();
        __syncthreads();

        const uint32_t aBase = smem_base + (s ? SMO_A1 : SMO_A0);
        const uint32_t bBase = smem_base + SMO_B;

        #pragma unroll
        for (int kk = 0; kk < 8; kk++) {
            const int k0 = kk * 16;

            uint32_t a[2][4];
            {
                const int col = k0 + (int)colselA;
                const uint32_t chi = (col >= 64) ? 16384u : 0u;
                const uint32_t clo = (uint32_t)((col & 63) << 1);
                #pragma unroll
                for (int mf = 0; mf < 2; mf++) {
                    const uint32_t addr = aBase + rbA[mf] + chi + (clo ^ sxA[mf]);
                    ldsm4(addr, a[mf][0], a[mf][1], a[mf][2], a[mf][3]);
                }
            }

            uint32_t b[8][2];
            {
                const int col = k0 + (int)colselB;
                const uint32_t chi = (col >= 64) ? 16384u : 0u;
                const uint32_t clo = (uint32_t)((col & 63) << 1);
                #pragma unroll
                for (int p = 0; p < 4; p++) {
                    const uint32_t addr = bBase + rbB[p] + chi + (clo ^ sxB[p]);
                    uint32_t r0, r1, r2, r3;
                    ldsm4(addr, r0, r1, r2, r3);
                    b[2 * p][0]     = r0;
                    b[2 * p][1]     = r1;
                    b[2 * p + 1][0] = r2;
                    b[2 * p + 1][1] = r3;
                }
            }

            #pragma unroll
            for (int mf = 0; mf < 2; mf++)
                #pragma unroll
                for (int nf = 0; nf < 8; nf++)
                    mma16816(acc[mf][nf], a[mf][0], a[mf][1], a[mf][2], a[mf][3],
                             b[nf][0], b[nf][1]);
        }
    }

    unsigned* words_s = (unsigned*)(sm + SMO_WRD);
    const int q2 = (lane & 3) * 2;
    const int g  = lane >> 2;

    #pragma unroll
    for (int mf = 0; mf < 2; mf++) {
        #pragma unroll
        for (int nc = 0; nc < 2; nc++) {
            unsigned lo = 0, hi = 0;
            #pragma unroll
            for (int f2 = 0; f2 < 4; f2++) {
                const int fi = nc * 4 + f2;
                lo |= (acc[mf][fi][0] > 0.0f ? 1u : 0u) << (8 * f2 + q2);
                lo |= (acc[mf][fi][1] > 0.0f ? 1u : 0u) << (8 * f2 + q2 + 1);
                hi |= (acc[mf][fi][2] > 0.0f ? 1u : 0u) << (8 * f2 + q2);
                hi |= (acc[mf][fi][3] > 0.0f ? 1u : 0u) << (8 * f2 + q2 + 1);
            }
            lo |= __shfl_xor_sync(0xffffffffu, lo, 1);
            lo |= __shfl_xor_sync(0xffffffffu, lo, 2);
            hi |= __shfl_xor_sync(0xffffffffu, hi, 1);
            hi |= __shfl_xor_sync(0xffffffffu, hi, 2);
            if ((lane & 3) == 0) {
                const int cw = (wn >> 5) + nc;
                words_s[(wm + mf * 16 + g) * 4 + cw]     = lo;
                words_s[(wm + mf * 16 + g + 8) * 4 + cw] = hi;
            }
        }
    }
    __syncthreads();

    if (tid < 128) {
        const uint4 w = *(const uint4*)&words_s[tid * 4];
        *(uint4*)&g_hv[(mt * 128 + tid) * HV_W + nt * 4] = w;
    }
}

// =================================================================================
// Stage 3: binary dot as int8 IMMA GEMM (R14-proven mainloop). Partials now packed
// u16x2 (adjacent columns share an accumulator quad; per-split max 2560 < 65535).
// =================================================================================
#define S3_B0   0
#define S3_B1   16384
#define S3_A0   32768
#define S3_A1   49152
#define S3_W0   65536
#define S3_W1   67584
#define S3_TOT  69632

__global__ void __launch_bounds__(256, 2) stage3_kernel()
{
    extern __shared__ char sm[];
    const uint32_t base = smem_u32(sm);
    const int tid = threadIdx.x, lane = tid & 31, wid = tid >> 5;
    const int ks = blockIdx.x, mt = blockIdx.y;
    const int t0   = ks * 20;
    const int tcnt = (ks < 3) ? 20 : 19;

    // prologue: B(t0) via cp.async; W(t0) -> staging0; preload W(t0+1) regs
    {
        const uint4* src = g_proto8 + t0 * 1024;
        #pragma unroll
        for (int i = 0; i < 4; i++) {
            const int j = tid + i * 256;
            CP_ASYNC16(base + S3_B0 + j * 16, (const void*)(src + j));
        }
        CP_COMMIT();
    }
    const int erow = tid >> 1;
    const int ewd  = (tid & 1) * 2;
    {
        const uint2 w = *(const uint2*)&g_hv[(mt * 128 + erow) * HV_W + t0 * 4 + ewd];
        *(uint2*)(sm + S3_W0 + (erow * 4 + ewd) * 4) = w;
    }
    uint2 Wn = make_uint2(0u, 0u);
    if (tcnt > 1)
        Wn = *(const uint2*)&g_hv[(mt * 128 + erow) * HV_W + (t0 + 1) * 4 + ewd];
    __syncthreads();

    // warp tiles: 32m x 64n
    const int wm = (wid & 3) * 32;
    const int wn = (wid >> 2) * 64;

    int arow[2];
    #pragma unroll
    for (int mf = 0; mf < 2; mf++) arow[mf] = wm + mf * 16 + (lane & 15);
    const int aslotb = (lane >> 4) & 1;

    int brow[4];
    #pragma unroll
    for (int p = 0; p < 4; p++) brow[p] = wn + p * 16 + (lane & 7) + ((lane & 16) >> 1);
    const int bslotb = (lane >> 3) & 1;

    int acc[2][8][4];
    #pragma unroll
    for (int mf = 0; mf < 2; mf++)
        #pragma unroll
        for (int nf = 0; nf < 8; nf++)
            #pragma unroll
            for (int i = 0; i < 4; i++) acc[mf][nf][i] = 0;

    for (int j = 0; j < tcnt; j++) {
        const uint32_t Ab = base + ((j & 1) ? S3_A1 : S3_A0);
        const uint32_t Bb = base + ((j & 1) ? S3_B1 : S3_B0);
        const unsigned* wsrc = (const unsigned*)(sm + ((j & 1) ? S3_W1 : S3_W0));

        // expand staging[j&1] -> Abuf[j&1] (warp owns one 128B row per step; conflict-free)
        #pragma unroll
        for (int i = 0; i < 16; i++) {
            const int oi  = tid + i * 256;      // 0..4095
            const int row = oi >> 5;
            const int rst = oi & 31;
            const int wd  = rst >> 3;
            const int q   = rst & 7;
            const uint32_t w = wsrc[row * 4 + wd];
            const uint32_t n = (w >> (q * 4)) & 0xFu;
            const uint32_t v = (n * 0x00204081u) & 0x01010101u;
            const int slot = wd * 2 + (q >> 2);
            *(uint32_t*)(sm + (((j & 1) ? S3_A1 : S3_A0)
                         + row * 128 + ((slot ^ (row & 7)) << 4) + (q & 3) * 4)) = v;
        }

        // prefetch: staging[(j+1)&1] <- Wn ; Wn <- W(j+2) ; B(j+1) cp.async
        if (j + 1 < tcnt)
            *(uint2*)(sm + ((j & 1) ? S3_W0 : S3_W1) + (erow * 4 + ewd) * 4) = Wn;
        if (j + 2 < tcnt)
            Wn = *(const uint2*)&g_hv[(mt * 128 + erow) * HV_W + (t0 + j + 2) * 4 + ewd];
        if (j + 1 < tcnt) {
            const uint4* src = g_proto8 + (t0 + j + 1) * 1024;
            const uint32_t bDst = base + ((j & 1) ? S3_B0 : S3_B1);
            #pragma unroll
            for (int i = 0; i < 4; i++) {
                const int jj = tid + i * 256;
                CP_ASYNC16(bDst + jj * 16, (const void*)(src + jj));
            }
        }
        CP_COMMIT();

        cp_wait<1>();
        __syncthreads();   // A expanded + staging written + B(j) ready

        #pragma unroll
        for (int k4 = 0; k4 < 4; k4++) {
            uint32_t a[2][4];
            #pragma unroll
            for (int mf = 0; mf < 2; mf++) {
                const int r = arow[mf];
                const int slot = k4 * 2 + aslotb;
                ldsm4(Ab + r * 128 + ((slot ^ (r & 7)) << 4),
                      a[mf][0], a[mf][1], a[mf][2], a[mf][3]);
            }
            uint32_t b[8][2];
            #pragma unroll
            for (int p = 0; p < 4; p++) {
                const int r = brow[p];
                const int slot = k4 * 2 + bslotb;
                uint32_t r0, r1, r2, r3;
                ldsm4(Bb + r * 128 + ((slot ^ (r & 7)) << 4), r0, r1, r2, r3);
                b[2 * p][0]     = r0;
                b[2 * p][1]     = r1;
                b[2 * p + 1][0] = r2;
                b[2 * p + 1][1] = r3;
            }
            #pragma unroll
            for (int mf = 0; mf < 2; mf++)
                #pragma unroll
                for (int nf = 0; nf < 8; nf++)
                    imma16832(acc[mf][nf], a[mf][0], a[mf][1], a[mf][2], a[mf][3],
                              b[nf][0], b[nf][1]);
        }
        __syncthreads();   // bufs consumed before next overwrite
    }

    // write partials packed u16x2 (adjacent cols c, c+1)
    unsigned* pd = g_pd + ((size_t)ks * BN + mt * 128) * 64;
    #pragma unroll
    for (int mf = 0; mf < 2; mf++) {
        const int r = wm + mf * 16 + (lane >> 2);
        #pragma unroll
        for (int nf = 0; nf < 8; nf++) {
            const int cw = (wn >> 1) + nf * 4 + (lane & 3);
            pd[r * 64 + cw]       = (unsigned)acc[mf][nf][0] | ((unsigned)acc[mf][nf][1] << 16);
            pd[(r + 8) * 64 + cw] = (unsigned)acc[mf][nf][2] | ((unsigned)acc[mf][nf][3] << 16);
        }
    }
}

// =================================================================================
// Reduce + sims + argmax. 256 blocks x 32 rows. Packed u16x2 vadd2 sums (max 10112).
// rowpop = class-100 dot (word 50, lo16).
// =================================================================================
__global__ void __launch_bounds__(256) reduce_kernel(const float* __restrict__ counts,
                                                     float* __restrict__ out_pred_f,
                                                     int*   __restrict__ out_pred_i,
                                                     float* __restrict__ out_sims)
{
    __shared__ unsigned dots_s[32 * 64];   // 8 KB packed
    __shared__ float    sims_s[32 * CC];   // 12.8 KB

    const int tid = threadIdx.x;
    const int b0  = blockIdx.x * 32;

    #pragma unroll
    for (int i = 0; i < 8; i++) {
        const int idx = tid + i * 256;     // 0..2047
        const size_t o = (size_t)(b0 + (idx >> 6)) * 64 + (idx & 63);
        const unsigned s01 = __vadd2(g_pd[o], g_pd[(size_t)BN * 64 + o]);
        const unsigned s23 = __vadd2(g_pd[2 * (size_t)BN * 64 + o],
                                     g_pd[3 * (size_t)BN * 64 + o]);
        dots_s[idx] = __vadd2(s01, s23);
    }
    __syncthreads();

    for (int idx = tid; idx < 32 * CC; idx += 256) {
        const int r = idx / CC;
        const int c = idx - r * CC;
        const int rowpop = (int)(dots_s[r * 64 + 50] & 0xFFFFu);
        const int dt = (int)((dots_s[r * 64 + (c >> 1)] >> ((c & 1) * 16)) & 0xFFFFu);
        const int ham = rowpop + g_protopop[c] - 2 * dt;
        const float s = (counts[c] > 0.0f) ? (1.0f - (float)ham / 10000.0f) : 0.0f;
        sims_s[r * CC + c] = s;
        if (out_sims) out_sims[(size_t)(b0 + r) * CC + c] = s;
    }
    __syncthreads();

    if (tid < 32) {
        float best = sims_s[tid * CC];
        int   bidx = 0;
        for (int c = 1; c < CC; c++) {
            const float v = sims_s[tid * CC + c];
            if (v > best) { best = v; bidx = c; }
        }
        if (out_pred_f) out_pred_f[b0 + tid] = (float)bidx;
        if (out_pred_i) out_pred_i[b0 + tid] = bidx;
    }
}

// =================================================================================
// Launch
// =================================================================================
extern "C" void kernel_launch(void* const* d_in, const int* in_sizes, int n_in,
                              void* d_out, int out_size)
{
    const float* feat   = (const float*)d_in[0];
    const float* R      = (const float*)d_in[1];
    const void*  proto  = d_in[2];
    const float* counts = (const float*)d_in[3];

    cudaFuncSetAttribute(gemm_kernel, cudaFuncAttributeMaxDynamicSharedMemorySize, SM_TOT);
    cudaFuncSetAttribute(stage3_kernel, cudaFuncAttributeMaxDynamicSharedMemorySize, S3_TOT);

    prep_fused_kernel<<<PREP_BLOCKS, 256>>>(feat, R, proto);
    gemm_kernel<<<dim3(NT, MT), 256, SM_TOT>>>();
    stage3_kernel<<<dim3(4, MT), 256, S3_TOT>>>();

    float* outf   = (float*)d_out;
    float* pred_f = nullptr;
    int*   pred_i = nullptr;
    float* sims   = nullptr;
    if (out_size >= BN + BN * CC) {
        pred_f = outf;
        sims   = outf + BN;
    } else if (out_size >= BN * CC) {
        sims = outf;
    } else {
        pred_i = (int*)d_out;
    }

    reduce_kernel<<<256, 256>>>(counts, pred_f, pred_i, sims);
}

// round 17
// speedup vs baseline: 1.0146x; 1.0146x over previous
#include <cuda_runtime.h>
#include <cuda_fp16.h>
#include <cstdint>

// Problem constants
#define BN   8192      // batch
#define FK   128       // feature dim (GEMM K)
#define DD   10000     // hypervector dim
#define CC   100       // classes
#define HV_W 320       // padded u32 words per hv row

#define MT   64        // m tiles (8192/128)
#define NT   79        // n tiles (10112 padded / 128)
#define TILE_U4 2048   // uint4 per 128x128 fp16 tile (32 KB)

// prep grid partition
#define PA_BLOCKS 512                       // prep_a: 8192 rows x 16 kgroups / 256
#define PB_BLOCKS 316                       // prep_b: 8 kg x 10112 d / 256 (exact)
#define P8_BLOCKS 79                        // proto8 tile builders
#define PREP_BLOCKS (PA_BLOCKS + PB_BLOCKS + CC + P8_BLOCKS)

// ---------------- scratch (device globals; no allocation allowed) ----------------
__device__ unsigned g_hv[BN * HV_W];            // bitpacked hypervectors (~10.5 MB)
__device__ uint4    g_proto[80 * CC];           // packed prototypes [chunk][class]
__device__ int      g_protopop[CC];             // per-class popcount
__device__ uint4    g_Abf[2 * MT * TILE_U4];    // feat 2-split fp16 planes (4 MB)
__device__ uint4    g_Bbf[NT * TILE_U4];        // R fp16, tile-image layout (2.6 MB)
__device__ uint4    g_proto8[NT * 1024];        // int8 proto tiles [t][128n x 128k sw] (1.3 MB)
__device__ unsigned g_pd[4 * BN * 64];          // k-split partial dots u16x2 packed (8.4 MB)

// ============================ helpers ==============================
__device__ __forceinline__ uint32_t smem_u32(const void* p) {
    uint32_t a;
    asm("{ .reg .u64 t; cvta.to.shared.u64 t, %1; cvt.u32.u64 %0, t; }" : "=r"(a) : "l"(p));
    return a;
}

#define CP_ASYNC16(dst, src) \
    asm volatile("cp.async.cg.shared.global [%0], [%1], 16;" :: "r"(dst), "l"(src) : "memory")
#define CP_COMMIT() asm volatile("cp.async.commit_group;" ::: "memory")
template <int N>
__device__ __forceinline__ void cp_wait() {
    asm volatile("cp.async.wait_group %0;" :: "n"(N) : "memory");
}

__device__ __forceinline__ void ldsm4(uint32_t addr, uint32_t& r0, uint32_t& r1,
                                      uint32_t& r2, uint32_t& r3) {
    asm volatile("ldmatrix.sync.aligned.m8n8.x4.shared.b16 {%0,%1,%2,%3}, [%4];"
                 : "=r"(r0), "=r"(r1), "=r"(r2), "=r"(r3) : "r"(addr));
}

__device__ __forceinline__ void mma16816(float* c, uint32_t a0, uint32_t a1,
                                         uint32_t a2, uint32_t a3,
                                         uint32_t b0, uint32_t b1) {
    asm volatile(
        "mma.sync.aligned.m16n8k16.row.col.f32.f16.f16.f32 "
        "{%0,%1,%2,%3}, {%4,%5,%6,%7}, {%8,%9}, {%0,%1,%2,%3};"
        : "+f"(c[0]), "+f"(c[1]), "+f"(c[2]), "+f"(c[3])
        : "r"(a0), "r"(a1), "r"(a2), "r"(a3), "r"(b0), "r"(b1));
}

__device__ __forceinline__ void imma16832(int* c, uint32_t a0, uint32_t a1,
                                          uint32_t a2, uint32_t a3,
                                          uint32_t b0, uint32_t b1) {
    asm volatile(
        "mma.sync.aligned.m16n8k32.row.col.s32.s8.s8.s32 "
        "{%0,%1,%2,%3}, {%4,%5,%6,%7}, {%8,%9}, {%0,%1,%2,%3};"
        : "+r"(c[0]), "+r"(c[1]), "+r"(c[2]), "+r"(c[3])
        : "r"(a0), "r"(a1), "r"(a2), "r"(a3), "r"(b0), "r"(b1));
}

// blocked-atom SW128 byte offset within a 128x128 fp16 tile (atom = 8 rows x 64 halves)
__device__ __forceinline__ uint32_t tile_off(int row, int col) {
    const uint32_t b = (uint32_t)(((row >> 3) + (col >> 6) * 16) * 1024
                                  + (row & 7) * 128 + (col & 63) * 2);
    return b ^ ((b >> 3) & 0x70);
}

__device__ __forceinline__ unsigned pack_pair(float v0, float v1, float& r0, float& r1) {
    const __half h0 = __float2half(v0);
    const __half h1 = __float2half(v1);
    r0 = v0 - __half2float(h0);
    r1 = v1 - __half2float(h1);
    return ((unsigned)__half_as_ushort(h1) << 16) | __half_as_ushort(h0);
}

// =================================================================================
// Fused prep kernel: A fp16 split, B fp16 tiles, proto bit-pack, proto8 int8 tiles.
// =================================================================================
__global__ void __launch_bounds__(256) prep_fused_kernel(const float* __restrict__ feat,
                                                         const float* __restrict__ R,
                                                         const void*  __restrict__ proto_raw)
{
    const int bx = blockIdx.x;

    if (bx < PA_BLOCKS) {
        const int idx = bx * 256 + threadIdx.x;   // 8192 * 16
        const int b   = idx >> 4;
        const int kg  = idx & 15;
        const int t   = b >> 7, m = b & 127, k0 = kg * 8;

        const float4 x0 = *(const float4*)(feat + b * FK + k0);
        const float4 x1 = *(const float4*)(feat + b * FK + k0 + 4);

        float r[8];
        uint4 w0, w1;
        w0.x = pack_pair(x0.x, x0.y, r[0], r[1]);
        w0.y = pack_pair(x0.z, x0.w, r[2], r[3]);
        w0.z = pack_pair(x1.x, x1.y, r[4], r[5]);
        w0.w = pack_pair(x1.z, x1.w, r[6], r[7]);
        float d0, d1;
        w1.x = pack_pair(r[0], r[1], d0, d1);
        w1.y = pack_pair(r[2], r[3], d0, d1);
        w1.z = pack_pair(r[4], r[5], d0, d1);
        w1.w = pack_pair(r[6], r[7], d0, d1);

        const uint32_t o16 = tile_off(m, k0) >> 4;
        g_Abf[(0 * MT + t) * TILE_U4 + o16] = w0;
        g_Abf[(1 * MT + t) * TILE_U4 + o16] = w1;
        return;
    }

    if (bx < PA_BLOCKS + PB_BLOCKS) {
        // ---- prep B: thread handles one d, 16 consecutive k (MLP=16) ----
        const int idx = (bx - PA_BLOCKS) * 256 + threadIdx.x;   // 8 * 10112 exactly
        const int kg = idx / (NT * 128);
        const int d  = idx - kg * (NT * 128);
        const int t  = d >> 7, n = d & 127, k0 = kg * 16;

        float v[16];
        #pragma unroll
        for (int kk = 0; kk < 16; kk++)
            v[kk] = (d < DD) ? R[(k0 + kk) * DD + d] : 0.0f;

        uint4 wa, wb;
        {
            float s0, s1;
            wa.x = pack_pair(v[0],  v[1],  s0, s1);
            wa.y = pack_pair(v[2],  v[3],  s0, s1);
            wa.z = pack_pair(v[4],  v[5],  s0, s1);
            wa.w = pack_pair(v[6],  v[7],  s0, s1);
            wb.x = pack_pair(v[8],  v[9],  s0, s1);
            wb.y = pack_pair(v[10], v[11], s0, s1);
            wb.z = pack_pair(v[12], v[13], s0, s1);
            wb.w = pack_pair(v[14], v[15], s0, s1);
        }
        g_Bbf[t * TILE_U4 + (tile_off(n, k0) >> 4)]     = wa;
        g_Bbf[t * TILE_U4 + (tile_off(n, k0 + 8) >> 4)] = wb;
        return;
    }

    // ---- shared dtype detector for the two proto roles ----
    const int tid = threadIdx.x;
    __shared__ int s_f32bad, s_i32bad;
    if (tid == 0) { s_f32bad = 0; s_i32bad = 0; }
    __syncthreads();
    {
        const unsigned v = ((const unsigned*)proto_raw)[tid];
        if (v != 0u && v != 0x3F800000u) atomicOr(&s_f32bad, 1);
        if (v > 1u)                      atomicOr(&s_i32bad, 1);
    }
    __syncthreads();
    const int mode = (!s_f32bad) ? 2 : ((!s_i32bad) ? 1 : 0);   // 2=f32, 1=i32, 0=u8

    const unsigned char* p8  = (const unsigned char*)proto_raw;
    const int*           p32 = (const int*)proto_raw;
    const float*         pf  = (const float*)proto_raw;

    if (bx < PA_BLOCKS + PB_BLOCKS + CC) {
        // ---------------- pack prototypes (bits) + popcount ----------------
        const int c = bx - (PA_BLOCKS + PB_BLOCKS);

        int sum = 0;
        for (int w = tid; w < HV_W; w += 256) {
            unsigned word = 0;
            if (w < 313) {
                const int dbase = w * 32;
                #pragma unroll 8
                for (int j = 0; j < 32; j++) {
                    const int d = dbase + j;
                    if (d < DD) {
                        bool bit;
                        if (mode == 2)      bit = (pf[c * DD + d] != 0.0f);
                        else if (mode == 1) bit = (p32[c * DD + d] != 0);
                        else                bit = (p8[c * DD + d] != 0);
                        if (bit) word |= (1u << j);
                    }
                }
            }
            sum += __popc(word);
            ((unsigned*)g_proto)[((w >> 2) * CC + c) * 4 + (w & 3)] = word;
        }

        __shared__ int red[256];
        red[tid] = sum;
        __syncthreads();
        #pragma unroll
        for (int s = 128; s > 0; s >>= 1) {
            if (tid < s) red[tid] += red[tid + s];
            __syncthreads();
        }
        if (tid == 0) g_protopop[c] = red[0];
        return;
    }

    // ---------------- proto8 tiles: [t][128 n x 128 k] int8, swizzled 16B slots ----
    // class 100 = all-ones (rowpop); classes 101..127 = zeros.
    {
        const int t = bx - (PA_BLOCKS + PB_BLOCKS + CC);
        #pragma unroll
        for (int i = 0; i < 4; i++) {
            const int ch = tid + i * 256;     // 0..1023
            const int n  = ch >> 3;
            const int s  = ch & 7;
            uint32_t vw[4];
            #pragma unroll
            for (int wq = 0; wq < 4; wq++) {
                uint32_t b = 0;
                #pragma unroll
                for (int bj = 0; bj < 4; bj++) {
                    const int kk = s * 16 + wq * 4 + bj;
                    const int d  = t * 128 + kk;
                    unsigned bit = 0;
                    if (n == 100) bit = 1;
                    else if (n < 100 && d < DD) {
                        if (mode == 2)      bit = (pf[n * DD + d] != 0.0f) ? 1u : 0u;
                        else if (mode == 1) bit = (p32[n * DD + d] != 0) ? 1u : 0u;
                        else                bit = (p8[n * DD + d] != 0) ? 1u : 0u;
                    }
                    b |= bit << (8 * bj);
                }
                vw[wq] = b;
            }
            g_proto8[t * 1024 + n * 8 + (s ^ (n & 7))] = make_uint4(vw[0], vw[1], vw[2], vw[3]);
        }
    }
}

// =================================================================================
// GEMM kernel (R10-proven, VERBATIM): 128x128 tile per CTA, mma.sync fp16 HMMA,
// 2 fp16 split planes fully prefetched, smem 98.3 KB -> 2 CTAs/SM. Writes g_hv.
// =================================================================================
#define SMO_A0   0
#define SMO_A1   32768
#define SMO_B    65536
#define SMO_WRD  98304
#define SM_TOT   (SMO_WRD + 2048)

__global__ void __launch_bounds__(256, 2) gemm_kernel()
{
    extern __shared__ char sm[];
    const uint32_t smem_base = smem_u32(sm);
    const int tid  = threadIdx.x;
    const int lane = tid & 31, wid = tid >> 5;
    const int nt = blockIdx.x, mt = blockIdx.y;

    {
        const uint4* srcB = g_Bbf + nt * TILE_U4;
        #pragma unroll
        for (int i = 0; i < 8; i++) {
            const int j = tid + i * 256;
            CP_ASYNC16(smem_base + SMO_B + j * 16, (const void*)(srcB + j));
        }
        const uint4* srcA0 = g_Abf + (0 * MT + mt) * TILE_U4;
        #pragma unroll
        for (int i = 0; i < 8; i++) {
            const int j = tid + i * 256;
            CP_ASYNC16(smem_base + SMO_A0 + j * 16, (const void*)(srcA0 + j));
        }
        CP_COMMIT();
        const uint4* srcA1 = g_Abf + (1 * MT + mt) * TILE_U4;
        #pragma unroll
        for (int i = 0; i < 8; i++) {
            const int j = tid + i * 256;
            CP_ASYNC16(smem_base + SMO_A1 + j * 16, (const void*)(srcA1 + j));
        }
        CP_COMMIT();
    }

    const int wm = (wid & 3) * 32;
    const int wn = (wid >> 2) * 64;

    uint32_t rbA[2], sxA[2];
    #pragma unroll
    for (int mf = 0; mf < 2; mf++) {
        const int r = wm + mf * 16 + (lane & 15);
        rbA[mf] = (uint32_t)((r >> 3) * 1024 + (r & 7) * 128);
        sxA[mf] = (uint32_t)((r & 7) << 4);
    }
    const uint32_t colselA = (lane & 16) >> 1;

    uint32_t rbB[4], sxB[4];
    #pragma unroll
    for (int p = 0; p < 4; p++) {
        const int r = wn + p * 16 + (lane & 7) + ((lane & 16) >> 1);
        rbB[p] = (uint32_t)((r >> 3) * 1024 + (r & 7) * 128);
        sxB[p] = (uint32_t)((r & 7) << 4);
    }
    const uint32_t colselB = lane & 8;

    float acc[2][8][4];
    #pragma unroll
    for (int mf = 0; mf < 2; mf++)
        #pragma unroll
        for (int nf = 0; nf < 8; nf++)
            #pragma unroll
            for (int i = 0; i < 4; i++) acc[mf][nf][i] = 0.0f;

    #pragma unroll
    for (int s = 0; s < 2; s++) {
        if (s == 0) cp_wait<1>();
        else        cp_wait<0>();
        __syncthreads();

        const uint32_t aBase = smem_base + (s ? SMO_A1 : SMO_A0);
        const uint32_t bBase = smem_base + SMO_B;

        #pragma unroll
        for (int kk = 0; kk < 8; kk++) {
            const int k0 = kk * 16;

            uint32_t a[2][4];
            {
                const int col = k0 + (int)colselA;
                const uint32_t chi = (col >= 64) ? 16384u : 0u;
                const uint32_t clo = (uint32_t)((col & 63) << 1);
                #pragma unroll
                for (int mf = 0; mf < 2; mf++) {
                    const uint32_t addr = aBase + rbA[mf] + chi + (clo ^ sxA[mf]);
                    ldsm4(addr, a[mf][0], a[mf][1], a[mf][2], a[mf][3]);
                }
            }

            uint32_t b[8][2];
            {
                const int col = k0 + (int)colselB;
                const uint32_t chi = (col >= 64) ? 16384u : 0u;
                const uint32_t clo = (uint32_t)((col & 63) << 1);
                #pragma unroll
                for (int p = 0; p < 4; p++) {
                    const uint32_t addr = bBase + rbB[p] + chi + (clo ^ sxB[p]);
                    uint32_t r0, r1, r2, r3;
                    ldsm4(addr, r0, r1, r2, r3);
                    b[2 * p][0]     = r0;
                    b[2 * p][1]     = r1;
                    b[2 * p + 1][0] = r2;
                    b[2 * p + 1][1] = r3;
                }
            }

            #pragma unroll
            for (int mf = 0; mf < 2; mf++)
                #pragma unroll
                for (int nf = 0; nf < 8; nf++)
                    mma16816(acc[mf][nf], a[mf][0], a[mf][1], a[mf][2], a[mf][3],
                             b[nf][0], b[nf][1]);
        }
    }

    unsigned* words_s = (unsigned*)(sm + SMO_WRD);
    const int q2 = (lane & 3) * 2;
    const int g  = lane >> 2;

    #pragma unroll
    for (int mf = 0; mf < 2; mf++) {
        #pragma unroll
        for (int nc = 0; nc < 2; nc++) {
            unsigned lo = 0, hi = 0;
            #pragma unroll
            for (int f2 = 0; f2 < 4; f2++) {
                const int fi = nc * 4 + f2;
                lo |= (acc[mf][fi][0] > 0.0f ? 1u : 0u) << (8 * f2 + q2);
                lo |= (acc[mf][fi][1] > 0.0f ? 1u : 0u) << (8 * f2 + q2 + 1);
                hi |= (acc[mf][fi][2] > 0.0f ? 1u : 0u) << (8 * f2 + q2);
                hi |= (acc[mf][fi][3] > 0.0f ? 1u : 0u) << (8 * f2 + q2 + 1);
            }
            lo |= __shfl_xor_sync(0xffffffffu, lo, 1);
            lo |= __shfl_xor_sync(0xffffffffu, lo, 2);
            hi |= __shfl_xor_sync(0xffffffffu, hi, 1);
            hi |= __shfl_xor_sync(0xffffffffu, hi, 2);
            if ((lane & 3) == 0) {
                const int cw = (wn >> 5) + nc;
                words_s[(wm + mf * 16 + g) * 4 + cw]     = lo;
                words_s[(wm + mf * 16 + g + 8) * 4 + cw] = hi;
            }
        }
    }
    __syncthreads();

    if (tid < 128) {
        const uint4 w = *(const uint4*)&words_s[tid * 4];
        *(uint4*)&g_hv[(mt * 128 + tid) * HV_W + nt * 4] = w;
    }
}

// =================================================================================
// Stage 3: binary dot as int8 IMMA GEMM (R14-proven mainloop). Partials now packed
// u16x2 (adjacent columns share an accumulator quad; per-split max 2560 < 65535).
// =================================================================================
#define S3_B0   0
#define S3_B1   16384
#define S3_A0   32768
#define S3_A1   49152
#define S3_W0   65536
#define S3_W1   67584
#define S3_TOT  69632

__global__ void __launch_bounds__(256, 2) stage3_kernel()
{
    extern __shared__ char sm[];
    const uint32_t base = smem_u32(sm);
    const int tid = threadIdx.x, lane = tid & 31, wid = tid >> 5;
    const int ks = blockIdx.x, mt = blockIdx.y;
    const int t0   = ks * 20;
    const int tcnt = (ks < 3) ? 20 : 19;

    // prologue: B(t0) via cp.async; W(t0) -> staging0; preload W(t0+1) regs
    {
        const uint4* src = g_proto8 + t0 * 1024;
        #pragma unroll
        for (int i = 0; i < 4; i++) {
            const int j = tid + i * 256;
            CP_ASYNC16(base + S3_B0 + j * 16, (const void*)(src + j));
        }
        CP_COMMIT();
    }
    const int erow = tid >> 1;
    const int ewd  = (tid & 1) * 2;
    {
        const uint2 w = *(const uint2*)&g_hv[(mt * 128 + erow) * HV_W + t0 * 4 + ewd];
        *(uint2*)(sm + S3_W0 + (erow * 4 + ewd) * 4) = w;
    }
    uint2 Wn = make_uint2(0u, 0u);
    if (tcnt > 1)
        Wn = *(const uint2*)&g_hv[(mt * 128 + erow) * HV_W + (t0 + 1) * 4 + ewd];
    __syncthreads();

    // warp tiles: 32m x 64n
    const int wm = (wid & 3) * 32;
    const int wn = (wid >> 2) * 64;

    int arow[2];
    #pragma unroll
    for (int mf = 0; mf < 2; mf++) arow[mf] = wm + mf * 16 + (lane & 15);
    const int aslotb = (lane >> 4) & 1;

    int brow[4];
    #pragma unroll
    for (int p = 0; p < 4; p++) brow[p] = wn + p * 16 + (lane & 7) + ((lane & 16) >> 1);
    const int bslotb = (lane >> 3) & 1;

    int acc[2][8][4];
    #pragma unroll
    for (int mf = 0; mf < 2; mf++)
        #pragma unroll
        for (int nf = 0; nf < 8; nf++)
            #pragma unroll
            for (int i = 0; i < 4; i++) acc[mf][nf][i] = 0;

    for (int j = 0; j < tcnt; j++) {
        const uint32_t Ab = base + ((j & 1) ? S3_A1 : S3_A0);
        const uint32_t Bb = base + ((j & 1) ? S3_B1 : S3_B0);
        const unsigned* wsrc = (const unsigned*)(sm + ((j & 1) ? S3_W1 : S3_W0));

        // expand staging[j&1] -> Abuf[j&1] (warp owns one 128B row per step; conflict-free)
        #pragma unroll
        for (int i = 0; i < 16; i++) {
            const int oi  = tid + i * 256;      // 0..4095
            const int row = oi >> 5;
            const int rst = oi & 31;
            const int wd  = rst >> 3;
            const int q   = rst & 7;
            const uint32_t w = wsrc[row * 4 + wd];
            const uint32_t n = (w >> (q * 4)) & 0xFu;
            const uint32_t v = (n * 0x00204081u) & 0x01010101u;
            const int slot = wd * 2 + (q >> 2);
            *(uint32_t*)(sm + (((j & 1) ? S3_A1 : S3_A0)
                         + row * 128 + ((slot ^ (row & 7)) << 4) + (q & 3) * 4)) = v;
        }

        // prefetch: staging[(j+1)&1] <- Wn ; Wn <- W(j+2) ; B(j+1) cp.async
        if (j + 1 < tcnt)
            *(uint2*)(sm + ((j & 1) ? S3_W0 : S3_W1) + (erow * 4 + ewd) * 4) = Wn;
        if (j + 2 < tcnt)
            Wn = *(const uint2*)&g_hv[(mt * 128 + erow) * HV_W + (t0 + j + 2) * 4 + ewd];
        if (j + 1 < tcnt) {
            const uint4* src = g_proto8 + (t0 + j + 1) * 1024;
            const uint32_t bDst = base + ((j & 1) ? S3_B0 : S3_B1);
            #pragma unroll
            for (int i = 0; i < 4; i++) {
                const int jj = tid + i * 256;
                CP_ASYNC16(bDst + jj * 16, (const void*)(src + jj));
            }
        }
        CP_COMMIT();

        cp_wait<1>();
        __syncthreads();   // A expanded + staging written + B(j) ready

        #pragma unroll
        for (int k4 = 0; k4 < 4; k4++) {
            uint32_t a[2][4];
            #pragma unroll
            for (int mf = 0; mf < 2; mf++) {
                const int r = arow[mf];
                const int slot = k4 * 2 + aslotb;
                ldsm4(Ab + r * 128 + ((slot ^ (r & 7)) << 4),
                      a[mf][0], a[mf][1], a[mf][2], a[mf][3]);
            }
            uint32_t b[8][2];
            #pragma unroll
            for (int p = 0; p < 4; p++) {
                const int r = brow[p];
                const int slot = k4 * 2 + bslotb;
                uint32_t r0, r1, r2, r3;
                ldsm4(Bb + r * 128 + ((slot ^ (r & 7)) << 4), r0, r1, r2, r3);
                b[2 * p][0]     = r0;
                b[2 * p][1]     = r1;
                b[2 * p + 1][0] = r2;
                b[2 * p + 1][1] = r3;
            }
            #pragma unroll
            for (int mf = 0; mf < 2; mf++)
                #pragma unroll
                for (int nf = 0; nf < 8; nf++)
                    imma16832(acc[mf][nf], a[mf][0], a[mf][1], a[mf][2], a[mf][3],
                              b[nf][0], b[nf][1]);
        }
        __syncthreads();   // bufs consumed before next overwrite
    }

    // write partials packed u16x2 (adjacent cols c, c+1)
    unsigned* pd = g_pd + ((size_t)ks * BN + mt * 128) * 64;
    #pragma unroll
    for (int mf = 0; mf < 2; mf++) {
        const int r = wm + mf * 16 + (lane >> 2);
        #pragma unroll
        for (int nf = 0; nf < 8; nf++) {
            const int cw = (wn >> 1) + nf * 4 + (lane & 3);
            pd[r * 64 + cw]       = (unsigned)acc[mf][nf][0] | ((unsigned)acc[mf][nf][1] << 16);
            pd[(r + 8) * 64 + cw] = (unsigned)acc[mf][nf][2] | ((unsigned)acc[mf][nf][3] << 16);
        }
    }
}

// =================================================================================
// Reduce + sims + argmax. 256 blocks x 32 rows. Packed u16x2 vadd2 sums (max 10112).
// rowpop = class-100 dot (word 50, lo16).
// =================================================================================
__global__ void __launch_bounds__(256) reduce_kernel(const float* __restrict__ counts,
                                                     float* __restrict__ out_pred_f,
                                                     int*   __restrict__ out_pred_i,
                                                     float* __restrict__ out_sims)
{
    __shared__ unsigned dots_s[32 * 64];   // 8 KB packed
    __shared__ float    sims_s[32 * CC];   // 12.8 KB

    const int tid = threadIdx.x;
    const int b0  = blockIdx.x * 32;

    #pragma unroll
    for (int i = 0; i < 8; i++) {
        const int idx = tid + i * 256;     // 0..2047
        const size_t o = (size_t)(b0 + (idx >> 6)) * 64 + (idx & 63);
        const unsigned s01 = __vadd2(g_pd[o], g_pd[(size_t)BN * 64 + o]);
        const unsigned s23 = __vadd2(g_pd[2 * (size_t)BN * 64 + o],
                                     g_pd[3 * (size_t)BN * 64 + o]);
        dots_s[idx] = __vadd2(s01, s23);
    }
    __syncthreads();

    for (int idx = tid; idx < 32 * CC; idx += 256) {
        const int r = idx / CC;
        const int c = idx - r * CC;
        const int rowpop = (int)(dots_s[r * 64 + 50] & 0xFFFFu);
        const int dt = (int)((dots_s[r * 64 + (c >> 1)] >> ((c & 1) * 16)) & 0xFFFFu);
        const int ham = rowpop + g_protopop[c] - 2 * dt;
        const float s = (counts[c] > 0.0f) ? (1.0f - (float)ham / 10000.0f) : 0.0f;
        sims_s[r * CC + c] = s;
        if (out_sims) out_sims[(size_t)(b0 + r) * CC + c] = s;
    }
    __syncthreads();

    if (tid < 32) {
        float best = sims_s[tid * CC];
        int   bidx = 0;
        for (int c = 1; c < CC; c++) {
            const float v = sims_s[tid * CC + c];
            if (v > best) { best = v; bidx = c; }
        }
        if (out_pred_f) out_pred_f[b0 + tid] = (float)bidx;
        if (out_pred_i) out_pred_i[b0 + tid] = bidx;
    }
}

// =================================================================================
// Launch
// =================================================================================
extern "C" void kernel_launch(void* const* d_in, const int* in_sizes, int n_in,
                              void* d_out, int out_size)
{
    const float* feat   = (const float*)d_in[0];
    const float* R      = (const float*)d_in[1];
    const void*  proto  = d_in[2];
    const float* counts = (const float*)d_in[3];

    cudaFuncSetAttribute(gemm_kernel, cudaFuncAttributeMaxDynamicSharedMemorySize, SM_TOT);
    cudaFuncSetAttribute(stage3_kernel, cudaFuncAttributeMaxDynamicSharedMemorySize, S3_TOT);

    prep_fused_kernel<<<PREP_BLOCKS, 256>>>(feat, R, proto);
    gemm_kernel<<<dim3(NT, MT), 256, SM_TOT>>>();
    stage3_kernel<<<dim3(4, MT), 256, S3_TOT>>>();

    float* outf   = (float*)d_out;
    float* pred_f = nullptr;
    int*   pred_i = nullptr;
    float* sims   = nullptr;
    if (out_size >= BN + BN * CC) {
        pred_f = outf;
        sims   = outf + BN;
    } else if (out_size >= BN * CC) {
        sims = outf;
    } else {
        pred_i = (int*)d_out;
    }

    reduce_kernel<<<256, 256>>>(counts, pred_f, pred_i, sims);
}